// round 10
// baseline (speedup 1.0000x reference)
#include <cuda_runtime.h>

// FullyConnectedTensorProduct: B=2^20, MUL=8, DIM=32, 4 paths of 8x8x8.
// R10: R9's compute kernels verbatim (port-split weights: W0[u<2]+W1 in smem,
// rest in __constant__), but phases reordered W2 -> W0 -> W1 -> store o0 ->
// W3 -> store o1 so big live sets never coexist: peak regs ~80 ->
// __launch_bounds__(128,6) = 24 warps/SM (R9 was 20 at 96 regs).
// Inputs/outputs transpose-staged through stride-65 padded smem.

typedef unsigned long long u64;

#define ALPHA_F     0.08838834764831845f   /* 1/sqrt(128) */
#define INV_SQRT3_F 0.5773502691896258f
#define EPITCH 65
#define WSH_N 640                          /* 128 (W0 u<2) + 512 (W1) */

__constant__ __align__(16) float cw[2048];  // raw weights (8 KB)

static __device__ __forceinline__ u64 pk2(float lo, float hi) {
    u64 r;
    asm("mov.b64 %0, {%1, %2};"
        : "=l"(r) : "r"(__float_as_uint(lo)), "r"(__float_as_uint(hi)));
    return r;
}
static __device__ __forceinline__ u64 dup2(float x) { return pk2(x, x); }
static __device__ __forceinline__ void upk2(u64 v, float& lo, float& hi) {
    unsigned l_, h_;
    asm("mov.b64 {%0, %1}, %2;" : "=r"(l_), "=r"(h_) : "l"(v));
    lo = __uint_as_float(l_);
    hi = __uint_as_float(h_);
}
static __device__ __forceinline__ u64 ffma2(u64 a, u64 b, u64 c) {
    u64 d;
    asm("fma.rn.f32x2 %0, %1, %2, %3;" : "=l"(d) : "l"(a), "l"(b), "l"(c));
    return d;
}

// a[0..3] += s * cw[off..off+7]  (const port)
static __device__ __forceinline__ void wacc1(int off, u64 s, u64 a[4]) {
    ulonglong2 q0 = *(const ulonglong2*)(cw + off);
    ulonglong2 q1 = *(const ulonglong2*)(cw + off + 4);
    a[0] = ffma2(s, q0.x, a[0]);
    a[1] = ffma2(s, q0.y, a[1]);
    a[2] = ffma2(s, q1.x, a[2]);
    a[3] = ffma2(s, q1.y, a[3]);
}
// a[0..3] += s * wp[0..7]  (shared / L1 crossbar)
static __device__ __forceinline__ void waccS(const float* wp, u64 s, u64 a[4]) {
    ulonglong2 q0 = *(const ulonglong2*)wp;
    ulonglong2 q1 = *(const ulonglong2*)(wp + 4);
    a[0] = ffma2(s, q0.x, a[0]);
    a[1] = ffma2(s, q0.y, a[1]);
    a[2] = ffma2(s, q1.x, a[2]);
    a[3] = ffma2(s, q1.y, a[3]);
}

__global__ __launch_bounds__(128, 6)
void fctp_kernel(const float* __restrict__ x1,
                 const float* __restrict__ x2,
                 const float* __restrict__ wt,
                 float* __restrict__ out)
{
    extern __shared__ __align__(16) float smem[];
    float* wsh = smem;             // 640 floats: W0[u<2] raw, then W1*INV_SQRT3
    float* st  = smem + WSH_N;     // 128 * EPITCH staging

    const int tid = threadIdx.x;
    const size_t eBase = (size_t)blockIdx.x * 128;

    // ---- stage smem weights: [0:128)=wt[0:128), [128:640)=wt[512:1024)*INV3 ----
#pragma unroll
    for (int c = 0; c < 5; c++) {
        int i = tid + c * 128;
        wsh[i] = (i < 128) ? __ldg(wt + i)
                           : __ldg(wt + 384 + i) * INV_SQRT3_F;
    }

    // ---- stage inputs: x1*ALPHA at [e*65+0..31], x2 at [e*65+32..63] ----
    {
        const float4* g1 = (const float4*)(x1 + eBase * 32);
        const float4* g2 = (const float4*)(x2 + eBase * 32);
#pragma unroll
        for (int c = 0; c < 8; c++) {
            int lin = tid + c * 128;
            int e = lin >> 3, j = (lin & 7) << 2;
            float4 a = g1[lin];
            float* p = st + e * EPITCH + j;
            p[0] = a.x * ALPHA_F; p[1] = a.y * ALPHA_F;
            p[2] = a.z * ALPHA_F; p[3] = a.w * ALPHA_F;
            float4 b = g2[lin];
            float* q = st + e * EPITCH + 32 + j;
            q[0] = b.x; q[1] = b.y; q[2] = b.z; q[3] = b.w;
        }
    }
    __syncthreads();

    float* S = st + tid * EPITCH;

    // ---- s1 dups (raw s1 in smem is dead afterwards) ----
    u64 s1d[8];
#pragma unroll
    for (int u = 0; u < 8; u++) s1d[u] = dup2(S[u]);

    // ======== phase 1: W2 (const): out1[w,k] += v2[v,k]*(sum_u s1[u]W2) ========
    u64 o1[3][4] = {};
#pragma unroll
    for (int v = 0; v < 8; v++) {
        u64 a[4] = {};
#pragma unroll
        for (int u = 0; u < 8; u++)
            wacc1(1024 + u * 64 + v * 8, s1d[u], a);
#pragma unroll
        for (int k = 0; k < 3; k++) {
            u64 t = dup2(S[40 + v * 3 + k]);
#pragma unroll
            for (int wp = 0; wp < 4; wp++)
                o1[k][wp] = ffma2(t, a[wp], o1[k][wp]);
        }
    }

    // ======== phase 2: W0 (u<2 smem, rest const): out0[w] += s2[v]*(...) ========
    u64 o0[4] = {};
#pragma unroll
    for (int v = 0; v < 8; v++) {
        u64 a[4] = {};
        waccS(&wsh[0 * 64 + v * 8], s1d[0], a);
        waccS(&wsh[1 * 64 + v * 8], s1d[1], a);
#pragma unroll
        for (int u = 2; u < 8; u++)
            wacc1(u * 64 + v * 8, s1d[u], a);
        u64 t = dup2(S[32 + v]);
#pragma unroll
        for (int i = 0; i < 4; i++) o0[i] = ffma2(t, a[i], o0[i]);
    }
    // s1d dead here

    // ======== phase 3: W1 (smem, INV_SQRT3 folded): out0 += (v1.v2)*W1 ========
    {
        float v2l[24];
#pragma unroll
        for (int i = 0; i < 24; i++) v2l[i] = S[40 + i];
#pragma unroll
        for (int u = 0; u < 8; u++) {
            float a0 = S[8 + u * 3 + 0];
            float a1 = S[8 + u * 3 + 1];
            float a2 = S[8 + u * 3 + 2];
#pragma unroll
            for (int v = 0; v < 8; v++) {
                float p = a0 * v2l[v * 3 + 0];
                p = fmaf(a1, v2l[v * 3 + 1], p);
                p = fmaf(a2, v2l[v * 3 + 2], p);
                u64 pd = dup2(p);
                const float* wp = &wsh[128 + u * 64 + v * 8];
                ulonglong2 q0 = *(const ulonglong2*)wp;
                ulonglong2 q1 = *(const ulonglong2*)(wp + 4);
                o0[0] = ffma2(pd, q0.x, o0[0]);
                o0[1] = ffma2(pd, q0.y, o0[1]);
                o0[2] = ffma2(pd, q1.x, o0[2]);
                o0[3] = ffma2(pd, q1.y, o0[3]);
            }
        }
    }

    // ---- store o0 -> S[0..7] (s1 raw dead since dups); frees 8 regs ----
    {
        float r0, r1;
        upk2(o0[0], r0, r1); S[0] = r0; S[1] = r1;
        upk2(o0[1], r0, r1); S[2] = r0; S[3] = r1;
        upk2(o0[2], r0, r1); S[4] = r0; S[5] = r1;
        upk2(o0[3], r0, r1); S[6] = r0; S[7] = r1;
    }

    // ======== phase 4: W3 (const): out1[w,k] += v1[u,k]*(sum_v s2[v]W3) ========
    {
        u64 s2d[8];
#pragma unroll
        for (int v = 0; v < 8; v++) s2d[v] = dup2(S[32 + v]);
#pragma unroll
        for (int u = 0; u < 8; u++) {
            u64 a[4] = {};
#pragma unroll
            for (int v = 0; v < 8; v++)
                wacc1(1536 + u * 64 + v * 8, s2d[v], a);
#pragma unroll
            for (int k = 0; k < 3; k++) {
                u64 t = dup2(S[8 + u * 3 + k]);   // v1 (has ALPHA)
#pragma unroll
                for (int wp = 0; wp < 4; wp++)
                    o1[k][wp] = ffma2(t, a[wp], o1[k][wp]);
            }
        }
    }

    // ---- store o1 -> S[8..31] (v1 dead after W3) ----
#pragma unroll
    for (int k = 0; k < 3; k++)
#pragma unroll
        for (int wp = 0; wp < 4; wp++) {
            float lo, hi;
            upk2(o1[k][wp], lo, hi);
            S[8 + (2 * wp)     * 3 + k] = lo;
            S[8 + (2 * wp + 1) * 3 + k] = hi;
        }

    __syncthreads();

    // ---- coalesced drain of S[0..31] per element ----
    {
        float4* go = (float4*)(out + eBase * 32);
#pragma unroll
        for (int c = 0; c < 8; c++) {
            int lin = tid + c * 128;
            int e = lin >> 3, j = (lin & 7) << 2;
            const float* p = st + e * EPITCH + j;
            go[lin] = make_float4(p[0], p[1], p[2], p[3]);
        }
    }
}

extern "C" void kernel_launch(void* const* d_in, const int* in_sizes, int n_in,
                              void* d_out, int out_size)
{
    const float* x1 = (const float*)d_in[0];
    const float* x2 = (const float*)d_in[1];
    const float* wt = (const float*)d_in[2];
    float* out = (float*)d_out;

    // Copy raw weights into constant memory (D2D async: graph-capturable).
    cudaMemcpyToSymbolAsync(cw, wt, 2048 * sizeof(float), 0,
                            cudaMemcpyDeviceToDevice, 0);

    int nelem  = out_size / 32;                            // 2^20
    int blocks = nelem / 128;                              // 128 elements/block
    size_t smem = (WSH_N + 128 * EPITCH) * sizeof(float);  // 35840 B

    static bool attr_set = false;
    if (!attr_set) {
        cudaFuncSetAttribute(fctp_kernel,
                             cudaFuncAttributeMaxDynamicSharedMemorySize,
                             (int)smem);
        attr_set = true;
    }
    fctp_kernel<<<blocks, 128, smem>>>(x1, x2, wt, out);
}

// round 11
// speedup vs baseline: 1.2976x; 1.2976x over previous
#include <cuda_runtime.h>

// FullyConnectedTensorProduct: B=2^20, MUL=8, DIM=32, 4 paths of 8x8x8.
// R11: tensor-core rewrite. The op is 4 batched GEMMs with shared A-halves:
//   out0      = A1[B x 128] @ B1[128 x 8],  A1 = [s1 (x) s2 | v1.v2]
//   out1[:,k] = A2k[B x 128] @ B2[128 x 8], A2k = [s1 (x) v2k | v1k (x) s2]
// B1/B2 are the natural weight layout (tf32, INV_SQRT3 folded into W1).
// mma.sync.m16n8k8.tf32: lane (g,t) needs only v in {t, t+4} -> per-lane
// A-forming cache is 40 floats/element in registers. Inputs/outputs
// transpose-staged through stride-65 padded smem (as R9).

typedef unsigned int u32;

#define ALPHA_F     0.08838834764831845f   /* 1/sqrt(128) */
#define INV_SQRT3_F 0.5773502691896258f
#define EPITCH 65

static __device__ __forceinline__ u32 cvt_tf32(float f) {
    u32 r;
    asm("cvt.rna.tf32.f32 %0, %1;" : "=r"(r) : "f"(f));
    return r;
}

static __device__ __forceinline__ void mma_tf32(float c[4],
        u32 a0, u32 a1, u32 a2, u32 a3, u32 b0, u32 b1)
{
    asm("mma.sync.aligned.m16n8k8.row.col.f32.tf32.tf32.f32 "
        "{%0,%1,%2,%3}, {%4,%5,%6,%7}, {%8,%9}, {%0,%1,%2,%3};"
        : "+f"(c[0]), "+f"(c[1]), "+f"(c[2]), "+f"(c[3])
        : "r"(a0), "r"(a1), "r"(a2), "r"(a3), "r"(b0), "r"(b1));
}

__global__ __launch_bounds__(128, 4)
void fctp_kernel(const float* __restrict__ x1,
                 const float* __restrict__ x2,
                 const float* __restrict__ wt,
                 float* __restrict__ out)
{
    extern __shared__ __align__(16) float smem[];
    u32*   wsu = (u32*)smem;          // 2048 tf32 weights (B1 | B2)
    float* st  = smem + 2048;         // 128 * EPITCH staging

    const int tid = threadIdx.x;
    const size_t eBase = (size_t)blockIdx.x * 128;

    // ---- stage weights as tf32; INV_SQRT3 folded into W1 [512,1024) ----
#pragma unroll
    for (int c = 0; c < 16; c++) {
        int i = tid + c * 128;
        float s = ((i >> 9) == 1) ? INV_SQRT3_F : 1.0f;
        wsu[i] = cvt_tf32(__ldg(wt + i) * s);
    }

    // ---- stage inputs: x1*ALPHA at [e*65+0..31], x2 at [e*65+32..63] ----
    {
        const float4* g1 = (const float4*)(x1 + eBase * 32);
        const float4* g2 = (const float4*)(x2 + eBase * 32);
#pragma unroll
        for (int c = 0; c < 8; c++) {
            int lin = tid + c * 128;
            int e = lin >> 3, j = (lin & 7) << 2;
            float4 a = g1[lin];
            float* p = st + e * EPITCH + j;
            p[0] = a.x * ALPHA_F; p[1] = a.y * ALPHA_F;
            p[2] = a.z * ALPHA_F; p[3] = a.w * ALPHA_F;
            float4 b = g2[lin];
            float* q = st + e * EPITCH + 32 + j;
            q[0] = b.x; q[1] = b.y; q[2] = b.z; q[3] = b.w;
        }
    }
    __syncthreads();

    const int lane = tid & 31;
    const int g = lane >> 2;          // 0..7  (row within 8-row group)
    const int t = lane & 3;           // 0..3  (k/col subgroup)
    const int wBase = (tid >> 5) * 32;   // this warp's element range

#pragma unroll
    for (int rb = 0; rb < 2; rb++) {
        float* Rlo = st + (wBase + rb * 16 + g) * EPITCH;
        float* Rhi = Rlo + 8 * EPITCH;

        // ---- per-lane cache: all u, but only v in {t, t+4} ----
        float s1l[8], s1h[8], v1l[8][3], v1h[8][3];
        float s2l[2], s2h[2], v2l[2][3], v2h[2][3];
#pragma unroll
        for (int u = 0; u < 8; u++) {
            s1l[u] = Rlo[u];
            s1h[u] = Rhi[u];
#pragma unroll
            for (int k = 0; k < 3; k++) {
                v1l[u][k] = Rlo[8 + u * 3 + k];
                v1h[u][k] = Rhi[8 + u * 3 + k];
            }
        }
#pragma unroll
        for (int j = 0; j < 2; j++) {
            int v = t + 4 * j;
            s2l[j] = Rlo[32 + v];
            s2h[j] = Rhi[32 + v];
#pragma unroll
            for (int k = 0; k < 3; k++) {
                v2l[j][k] = Rlo[40 + v * 3 + k];
                v2h[j][k] = Rhi[40 + v * 3 + k];
            }
        }

        // ---- GEMM1: out0 (two accumulator chains for MMA ILP) ----
        float C0a[4] = {0.f, 0.f, 0.f, 0.f};
        float C0b[4] = {0.f, 0.f, 0.f, 0.f};
#pragma unroll
        for (int kk = 0; kk < 8; kk++) {        // cols 0..63: s1 (x) s2
            u32 b0 = wsu[(kk * 8 + t) * 8 + g];
            u32 b1 = wsu[(kk * 8 + t + 4) * 8 + g];
            u32 a0 = cvt_tf32(s1l[kk] * s2l[0]);
            u32 a1 = cvt_tf32(s1h[kk] * s2h[0]);
            u32 a2 = cvt_tf32(s1l[kk] * s2l[1]);
            u32 a3 = cvt_tf32(s1h[kk] * s2h[1]);
            mma_tf32(C0a, a0, a1, a2, a3, b0, b1);
        }
#pragma unroll
        for (int kk = 8; kk < 16; kk++) {       // cols 64..127: v1 . v2
            int u = kk - 8;
            u32 b0 = wsu[(kk * 8 + t) * 8 + g];
            u32 b1 = wsu[(kk * 8 + t + 4) * 8 + g];
            u32 a0 = cvt_tf32(v1l[u][0] * v2l[0][0] + v1l[u][1] * v2l[0][1]
                              + v1l[u][2] * v2l[0][2]);
            u32 a1 = cvt_tf32(v1h[u][0] * v2h[0][0] + v1h[u][1] * v2h[0][1]
                              + v1h[u][2] * v2h[0][2]);
            u32 a2 = cvt_tf32(v1l[u][0] * v2l[1][0] + v1l[u][1] * v2l[1][1]
                              + v1l[u][2] * v2l[1][2]);
            u32 a3 = cvt_tf32(v1h[u][0] * v2h[1][0] + v1h[u][1] * v2h[1][1]
                              + v1h[u][2] * v2h[1][2]);
            mma_tf32(C0b, a0, a1, a2, a3, b0, b1);
        }

        // ---- GEMM2: out1, 3 k-planes share each B fragment ----
        float C1[3][4] = {};
#pragma unroll
        for (int kk = 0; kk < 8; kk++) {        // cols 0..63: s1 (x) v2k
            u32 b0 = wsu[1024 + (kk * 8 + t) * 8 + g];
            u32 b1 = wsu[1024 + (kk * 8 + t + 4) * 8 + g];
#pragma unroll
            for (int k = 0; k < 3; k++) {
                u32 a0 = cvt_tf32(s1l[kk] * v2l[0][k]);
                u32 a1 = cvt_tf32(s1h[kk] * v2h[0][k]);
                u32 a2 = cvt_tf32(s1l[kk] * v2l[1][k]);
                u32 a3 = cvt_tf32(s1h[kk] * v2h[1][k]);
                mma_tf32(C1[k], a0, a1, a2, a3, b0, b1);
            }
        }
#pragma unroll
        for (int kk = 8; kk < 16; kk++) {       // cols 64..127: v1k (x) s2
            int u = kk - 8;
            u32 b0 = wsu[1024 + (kk * 8 + t) * 8 + g];
            u32 b1 = wsu[1024 + (kk * 8 + t + 4) * 8 + g];
#pragma unroll
            for (int k = 0; k < 3; k++) {
                u32 a0 = cvt_tf32(v1l[u][k] * s2l[0]);
                u32 a1 = cvt_tf32(v1h[u][k] * s2h[0]);
                u32 a2 = cvt_tf32(v1l[u][k] * s2l[1]);
                u32 a3 = cvt_tf32(v1h[u][k] * s2h[1]);
                mma_tf32(C1[k], a0, a1, a2, a3, b0, b1);
            }
        }

        // ---- store into own staging rows (s1/v1 regions now dead) ----
        // C layout: c0:(g,2t) c1:(g,2t+1) c2:(g+8,2t) c3:(g+8,2t+1)
        Rlo[2 * t]     = C0a[0] + C0b[0];
        Rlo[2 * t + 1] = C0a[1] + C0b[1];
        Rhi[2 * t]     = C0a[2] + C0b[2];
        Rhi[2 * t + 1] = C0a[3] + C0b[3];
#pragma unroll
        for (int k = 0; k < 3; k++) {
            Rlo[8 + (2 * t) * 3 + k]     = C1[k][0];
            Rlo[8 + (2 * t + 1) * 3 + k] = C1[k][1];
            Rhi[8 + (2 * t) * 3 + k]     = C1[k][2];
            Rhi[8 + (2 * t + 1) * 3 + k] = C1[k][3];
        }
    }

    __syncthreads();

    // ---- coalesced drain of S[0..31] per element ----
    {
        float4* go = (float4*)(out + eBase * 32);
#pragma unroll
        for (int c = 0; c < 8; c++) {
            int lin = tid + c * 128;
            int e = lin >> 3, j = (lin & 7) << 2;
            const float* p = st + e * EPITCH + j;
            go[lin] = make_float4(p[0], p[1], p[2], p[3]);
        }
    }
}

extern "C" void kernel_launch(void* const* d_in, const int* in_sizes, int n_in,
                              void* d_out, int out_size)
{
    const float* x1 = (const float*)d_in[0];
    const float* x2 = (const float*)d_in[1];
    const float* wt = (const float*)d_in[2];
    float* out = (float*)d_out;

    int nelem  = out_size / 32;                            // 2^20
    int blocks = nelem / 128;                              // 128 elements/block
    size_t smem = (2048 + 128 * EPITCH) * sizeof(float);   // 41472 B

    static bool attr_set = false;
    if (!attr_set) {
        cudaFuncSetAttribute(fctp_kernel,
                             cudaFuncAttributeMaxDynamicSharedMemorySize,
                             (int)smem);
        attr_set = true;
    }
    fctp_kernel<<<blocks, 128, smem>>>(x1, x2, wt, out);
}

// round 12
// speedup vs baseline: 1.4680x; 1.1314x over previous
#include <cuda_runtime.h>

// FullyConnectedTensorProduct: B=2^20, MUL=8, DIM=32, 4 paths of 8x8x8.
// R12: R11 tensor-core kernel with A-fragment cvt.rna.tf32 replaced by raw
// f32 bit-casts (HMMA tf32 ignores low mantissa bits -> free RZ truncation;
// CUTLASS fast path). Removes 512 ALU/issue slots per warp-iter (alu was 43%).
// Weights still cvt.rna at staging. Same fragment layout / staging as R11.

typedef unsigned int u32;

#define ALPHA_F     0.08838834764831845f   /* 1/sqrt(128) */
#define INV_SQRT3_F 0.5773502691896258f
#define EPITCH 65

static __device__ __forceinline__ u32 cvt_tf32(float f) {
    u32 r;
    asm("cvt.rna.tf32.f32 %0, %1;" : "=r"(r) : "f"(f));
    return r;
}
// raw f32 bits: HMMA reads tf32 from the top bits (RZ-truncated tf32)
static __device__ __forceinline__ u32 tf32_raw(float f) {
    return __float_as_uint(f);
}

static __device__ __forceinline__ void mma_tf32(float c[4],
        u32 a0, u32 a1, u32 a2, u32 a3, u32 b0, u32 b1)
{
    asm("mma.sync.aligned.m16n8k8.row.col.f32.tf32.tf32.f32 "
        "{%0,%1,%2,%3}, {%4,%5,%6,%7}, {%8,%9}, {%0,%1,%2,%3};"
        : "+f"(c[0]), "+f"(c[1]), "+f"(c[2]), "+f"(c[3])
        : "r"(a0), "r"(a1), "r"(a2), "r"(a3), "r"(b0), "r"(b1));
}

__global__ __launch_bounds__(128, 4)
void fctp_kernel(const float* __restrict__ x1,
                 const float* __restrict__ x2,
                 const float* __restrict__ wt,
                 float* __restrict__ out)
{
    extern __shared__ __align__(16) float smem[];
    u32*   wsu = (u32*)smem;          // 2048 tf32 weights (B1 | B2)
    float* st  = smem + 2048;         // 128 * EPITCH staging

    const int tid = threadIdx.x;
    const size_t eBase = (size_t)blockIdx.x * 128;

    // ---- stage weights as tf32 (RNA); INV_SQRT3 folded into W1 [512,1024) ----
#pragma unroll
    for (int c = 0; c < 16; c++) {
        int i = tid + c * 128;
        float s = ((i >> 9) == 1) ? INV_SQRT3_F : 1.0f;
        wsu[i] = cvt_tf32(__ldg(wt + i) * s);
    }

    // ---- stage inputs: x1*ALPHA at [e*65+0..31], x2 at [e*65+32..63] ----
    {
        const float4* g1 = (const float4*)(x1 + eBase * 32);
        const float4* g2 = (const float4*)(x2 + eBase * 32);
#pragma unroll
        for (int c = 0; c < 8; c++) {
            int lin = tid + c * 128;
            int e = lin >> 3, j = (lin & 7) << 2;
            float4 a = g1[lin];
            float* p = st + e * EPITCH + j;
            p[0] = a.x * ALPHA_F; p[1] = a.y * ALPHA_F;
            p[2] = a.z * ALPHA_F; p[3] = a.w * ALPHA_F;
            float4 b = g2[lin];
            float* q = st + e * EPITCH + 32 + j;
            q[0] = b.x; q[1] = b.y; q[2] = b.z; q[3] = b.w;
        }
    }
    __syncthreads();

    const int lane = tid & 31;
    const int g = lane >> 2;          // 0..7  (row within 8-row group)
    const int t = lane & 3;           // 0..3  (col subgroup)
    const int wBase = (tid >> 5) * 32;   // this warp's element range

#pragma unroll
    for (int rb = 0; rb < 2; rb++) {
        float* Rlo = st + (wBase + rb * 16 + g) * EPITCH;
        float* Rhi = Rlo + 8 * EPITCH;

        // ---- per-lane cache: all u, but only v in {t, t+4} ----
        float s1l[8], s1h[8], v1l[8][3], v1h[8][3];
        float s2l[2], s2h[2], v2l[2][3], v2h[2][3];
#pragma unroll
        for (int u = 0; u < 8; u++) {
            s1l[u] = Rlo[u];
            s1h[u] = Rhi[u];
#pragma unroll
            for (int k = 0; k < 3; k++) {
                v1l[u][k] = Rlo[8 + u * 3 + k];
                v1h[u][k] = Rhi[8 + u * 3 + k];
            }
        }
#pragma unroll
        for (int j = 0; j < 2; j++) {
            int v = t + 4 * j;
            s2l[j] = Rlo[32 + v];
            s2h[j] = Rhi[32 + v];
#pragma unroll
            for (int k = 0; k < 3; k++) {
                v2l[j][k] = Rlo[40 + v * 3 + k];
                v2h[j][k] = Rhi[40 + v * 3 + k];
            }
        }

        // ---- GEMM1: out0 (two accumulator chains for MMA ILP) ----
        float C0a[4] = {0.f, 0.f, 0.f, 0.f};
        float C0b[4] = {0.f, 0.f, 0.f, 0.f};
#pragma unroll
        for (int kk = 0; kk < 8; kk++) {        // cols 0..63: s1 (x) s2
            u32 b0 = wsu[(kk * 8 + t) * 8 + g];
            u32 b1 = wsu[(kk * 8 + t + 4) * 8 + g];
            u32 a0 = tf32_raw(s1l[kk] * s2l[0]);
            u32 a1 = tf32_raw(s1h[kk] * s2h[0]);
            u32 a2 = tf32_raw(s1l[kk] * s2l[1]);
            u32 a3 = tf32_raw(s1h[kk] * s2h[1]);
            mma_tf32(C0a, a0, a1, a2, a3, b0, b1);
        }
#pragma unroll
        for (int kk = 8; kk < 16; kk++) {       // cols 64..127: v1 . v2
            int u = kk - 8;
            u32 b0 = wsu[(kk * 8 + t) * 8 + g];
            u32 b1 = wsu[(kk * 8 + t + 4) * 8 + g];
            u32 a0 = tf32_raw(v1l[u][0] * v2l[0][0] + v1l[u][1] * v2l[0][1]
                              + v1l[u][2] * v2l[0][2]);
            u32 a1 = tf32_raw(v1h[u][0] * v2h[0][0] + v1h[u][1] * v2h[0][1]
                              + v1h[u][2] * v2h[0][2]);
            u32 a2 = tf32_raw(v1l[u][0] * v2l[1][0] + v1l[u][1] * v2l[1][1]
                              + v1l[u][2] * v2l[1][2]);
            u32 a3 = tf32_raw(v1h[u][0] * v2h[1][0] + v1h[u][1] * v2h[1][1]
                              + v1h[u][2] * v2h[1][2]);
            mma_tf32(C0b, a0, a1, a2, a3, b0, b1);
        }

        // ---- GEMM2: out1, 3 k-planes share each B fragment ----
        float C1[3][4] = {};
#pragma unroll
        for (int kk = 0; kk < 8; kk++) {        // cols 0..63: s1 (x) v2k
            u32 b0 = wsu[1024 + (kk * 8 + t) * 8 + g];
            u32 b1 = wsu[1024 + (kk * 8 + t + 4) * 8 + g];
#pragma unroll
            for (int k = 0; k < 3; k++) {
                u32 a0 = tf32_raw(s1l[kk] * v2l[0][k]);
                u32 a1 = tf32_raw(s1h[kk] * v2h[0][k]);
                u32 a2 = tf32_raw(s1l[kk] * v2l[1][k]);
                u32 a3 = tf32_raw(s1h[kk] * v2h[1][k]);
                mma_tf32(C1[k], a0, a1, a2, a3, b0, b1);
            }
        }
#pragma unroll
        for (int kk = 8; kk < 16; kk++) {       // cols 64..127: v1k (x) s2
            int u = kk - 8;
            u32 b0 = wsu[1024 + (kk * 8 + t) * 8 + g];
            u32 b1 = wsu[1024 + (kk * 8 + t + 4) * 8 + g];
#pragma unroll
            for (int k = 0; k < 3; k++) {
                u32 a0 = tf32_raw(v1l[u][k] * s2l[0]);
                u32 a1 = tf32_raw(v1h[u][k] * s2h[0]);
                u32 a2 = tf32_raw(v1l[u][k] * s2l[1]);
                u32 a3 = tf32_raw(v1h[u][k] * s2h[1]);
                mma_tf32(C1[k], a0, a1, a2, a3, b0, b1);
            }
        }

        // ---- store into own staging rows (s1/v1 regions now dead) ----
        // C layout: c0:(g,2t) c1:(g,2t+1) c2:(g+8,2t) c3:(g+8,2t+1)
        Rlo[2 * t]     = C0a[0] + C0b[0];
        Rlo[2 * t + 1] = C0a[1] + C0b[1];
        Rhi[2 * t]     = C0a[2] + C0b[2];
        Rhi[2 * t + 1] = C0a[3] + C0b[3];
#pragma unroll
        for (int k = 0; k < 3; k++) {
            Rlo[8 + (2 * t) * 3 + k]     = C1[k][0];
            Rlo[8 + (2 * t + 1) * 3 + k] = C1[k][1];
            Rhi[8 + (2 * t) * 3 + k]     = C1[k][2];
            Rhi[8 + (2 * t + 1) * 3 + k] = C1[k][3];
        }
    }

    __syncthreads();

    // ---- coalesced drain of S[0..31] per element ----
    {
        float4* go = (float4*)(out + eBase * 32);
#pragma unroll
        for (int c = 0; c < 8; c++) {
            int lin = tid + c * 128;
            int e = lin >> 3, j = (lin & 7) << 2;
            const float* p = st + e * EPITCH + j;
            go[lin] = make_float4(p[0], p[1], p[2], p[3]);
        }
    }
}

extern "C" void kernel_launch(void* const* d_in, const int* in_sizes, int n_in,
                              void* d_out, int out_size)
{
    const float* x1 = (const float*)d_in[0];
    const float* x2 = (const float*)d_in[1];
    const float* wt = (const float*)d_in[2];
    float* out = (float*)d_out;

    int nelem  = out_size / 32;                            // 2^20
    int blocks = nelem / 128;                              // 128 elements/block
    size_t smem = (2048 + 128 * EPITCH) * sizeof(float);   // 41472 B

    static bool attr_set = false;
    if (!attr_set) {
        cudaFuncSetAttribute(fctp_kernel,
                             cudaFuncAttributeMaxDynamicSharedMemorySize,
                             (int)smem);
        attr_set = true;
    }
    fctp_kernel<<<blocks, 128, smem>>>(x1, x2, wt, out);
}

// round 13
// speedup vs baseline: 1.5279x; 1.0408x over previous
#include <cuda_runtime.h>

// FullyConnectedTensorProduct: B=2^20, MUL=8, DIM=32, 4 paths of 8x8x8.
// R13: R12 tensor-core kernel with ALL smem traffic vectorized. EPITCH=68
// (rows 16B-aligned, banks 4g distinct) -> input cache via LDS.128 (1 wf),
// weights restaged in (b0,b1) pairs -> LDS.64, outputs via STS.64, staging
// via STS.128/LDS.128. A-fragments are raw f32 bits (free tf32 truncation).

typedef unsigned int u32;

#define ALPHA_F     0.08838834764831845f   /* 1/sqrt(128) */
#define INV_SQRT3_F 0.5773502691896258f
#define EPITCH 68

static __device__ __forceinline__ u32 cvt_tf32(float f) {
    u32 r;
    asm("cvt.rna.tf32.f32 %0, %1;" : "=r"(r) : "f"(f));
    return r;
}
static __device__ __forceinline__ u32 tf32_raw(float f) {
    return __float_as_uint(f);
}

static __device__ __forceinline__ void mma_tf32(float c[4],
        u32 a0, u32 a1, u32 a2, u32 a3, u32 b0, u32 b1)
{
    asm("mma.sync.aligned.m16n8k8.row.col.f32.tf32.tf32.f32 "
        "{%0,%1,%2,%3}, {%4,%5,%6,%7}, {%8,%9}, {%0,%1,%2,%3};"
        : "+f"(c[0]), "+f"(c[1]), "+f"(c[2]), "+f"(c[3])
        : "r"(a0), "r"(a1), "r"(a2), "r"(a3), "r"(b0), "r"(b1));
}

__global__ __launch_bounds__(128, 4)
void fctp_kernel(const float* __restrict__ x1,
                 const float* __restrict__ x2,
                 const float* __restrict__ wt,
                 float* __restrict__ out)
{
    extern __shared__ __align__(16) float smem[];
    uint2* wsp = (uint2*)smem;        // 1024 pairs: (b0,b1) per (kk,t,g)
    float* st  = smem + 2048;         // 128 * EPITCH staging

    const int tid = threadIdx.x;
    const size_t eBase = (size_t)blockIdx.x * 128;

    // ---- stage weights as paired tf32: float pos i = kk*64 + (t*8+g)*2 + j
    //      source c = kk*8 + t + 4*j (weight col), src idx = c*8 + g.
#pragma unroll
    for (int c = 0; c < 16; c++) {
        int i  = tid + c * 128;
        int kk = i >> 6;
        int p  = (i >> 1) & 31;       // t*8+g
        int j  = i & 1;
        int t_ = p >> 3, g_ = p & 7;
        int src = (kk * 8 + t_ + 4 * j) * 8 + g_;
        float s = ((src >> 9) == 1) ? INV_SQRT3_F : 1.0f;
        ((u32*)smem)[i] = cvt_tf32(__ldg(wt + src) * s);
    }

    // ---- stage inputs (vector STS.128): x1*ALPHA at [0..31], x2 at [32..63] ----
    {
        const float4* g1 = (const float4*)(x1 + eBase * 32);
        const float4* g2 = (const float4*)(x2 + eBase * 32);
#pragma unroll
        for (int c = 0; c < 8; c++) {
            int lin = tid + c * 128;
            int e = lin >> 3, j = (lin & 7) << 2;
            float4 a = g1[lin];
            a.x *= ALPHA_F; a.y *= ALPHA_F; a.z *= ALPHA_F; a.w *= ALPHA_F;
            *(float4*)(st + e * EPITCH + j) = a;
            float4 b = g2[lin];
            *(float4*)(st + e * EPITCH + 32 + j) = b;
        }
    }
    __syncthreads();

    const int lane = tid & 31;
    const int g = lane >> 2;          // 0..7
    const int t = lane & 3;           // 0..3
    const int wBase = (tid >> 5) * 32;

#pragma unroll
    for (int rb = 0; rb < 2; rb++) {
        float* Rlo = st + (wBase + rb * 16 + g) * EPITCH;
        float* Rhi = Rlo + 8 * EPITCH;

        // ---- vector input cache: s1 (2x float4/row), v1 (6x float4/row) ----
        float4 s1lq0 = *(const float4*)(Rlo + 0);
        float4 s1lq1 = *(const float4*)(Rlo + 4);
        float4 s1hq0 = *(const float4*)(Rhi + 0);
        float4 s1hq1 = *(const float4*)(Rhi + 4);
        float s1l[8] = {s1lq0.x, s1lq0.y, s1lq0.z, s1lq0.w,
                        s1lq1.x, s1lq1.y, s1lq1.z, s1lq1.w};
        float s1h[8] = {s1hq0.x, s1hq0.y, s1hq0.z, s1hq0.w,
                        s1hq1.x, s1hq1.y, s1hq1.z, s1hq1.w};
        float v1l[24], v1h[24];
#pragma unroll
        for (int q = 0; q < 6; q++) {
            float4 a = *(const float4*)(Rlo + 8 + 4 * q);
            v1l[4*q+0] = a.x; v1l[4*q+1] = a.y; v1l[4*q+2] = a.z; v1l[4*q+3] = a.w;
            float4 b = *(const float4*)(Rhi + 8 + 4 * q);
            v1h[4*q+0] = b.x; v1h[4*q+1] = b.y; v1h[4*q+2] = b.z; v1h[4*q+3] = b.w;
        }
        // s2 / v2: only v in {t, t+4} (scalar, unaligned offsets)
        float s2l[2], s2h[2], v2l[2][3], v2h[2][3];
#pragma unroll
        for (int j = 0; j < 2; j++) {
            int v = t + 4 * j;
            s2l[j] = Rlo[32 + v];
            s2h[j] = Rhi[32 + v];
#pragma unroll
            for (int k = 0; k < 3; k++) {
                v2l[j][k] = Rlo[40 + v * 3 + k];
                v2h[j][k] = Rhi[40 + v * 3 + k];
            }
        }

        const int wIdx = t * 8 + g;   // pair index within a kk block

        // ---- GEMM1: out0 ----
        float C0a[4] = {0.f, 0.f, 0.f, 0.f};
        float C0b[4] = {0.f, 0.f, 0.f, 0.f};
#pragma unroll
        for (int kk = 0; kk < 8; kk++) {        // cols 0..63: s1 (x) s2
            uint2 wv = wsp[kk * 32 + wIdx];
            mma_tf32(C0a,
                     tf32_raw(s1l[kk] * s2l[0]), tf32_raw(s1h[kk] * s2h[0]),
                     tf32_raw(s1l[kk] * s2l[1]), tf32_raw(s1h[kk] * s2h[1]),
                     wv.x, wv.y);
        }
#pragma unroll
        for (int kk = 8; kk < 16; kk++) {       // cols 64..127: v1 . v2
            int u = kk - 8;
            uint2 wv = wsp[kk * 32 + wIdx];
            u32 a0 = tf32_raw(v1l[u*3+0] * v2l[0][0] + v1l[u*3+1] * v2l[0][1]
                              + v1l[u*3+2] * v2l[0][2]);
            u32 a1 = tf32_raw(v1h[u*3+0] * v2h[0][0] + v1h[u*3+1] * v2h[0][1]
                              + v1h[u*3+2] * v2h[0][2]);
            u32 a2 = tf32_raw(v1l[u*3+0] * v2l[1][0] + v1l[u*3+1] * v2l[1][1]
                              + v1l[u*3+2] * v2l[1][2]);
            u32 a3 = tf32_raw(v1h[u*3+0] * v2h[1][0] + v1h[u*3+1] * v2h[1][1]
                              + v1h[u*3+2] * v2h[1][2]);
            mma_tf32(C0b, a0, a1, a2, a3, wv.x, wv.y);
        }

        // ---- GEMM2: out1 (kk blocks 16..31) ----
        float C1[3][4] = {};
#pragma unroll
        for (int kk = 0; kk < 8; kk++) {        // cols 0..63: s1 (x) v2k
            uint2 wv = wsp[(16 + kk) * 32 + wIdx];
#pragma unroll
            for (int k = 0; k < 3; k++) {
                mma_tf32(C1[k],
                         tf32_raw(s1l[kk] * v2l[0][k]), tf32_raw(s1h[kk] * v2h[0][k]),
                         tf32_raw(s1l[kk] * v2l[1][k]), tf32_raw(s1h[kk] * v2h[1][k]),
                         wv.x, wv.y);
            }
        }
#pragma unroll
        for (int kk = 8; kk < 16; kk++) {       // cols 64..127: v1k (x) s2
            int u = kk - 8;
            uint2 wv = wsp[(16 + kk) * 32 + wIdx];
#pragma unroll
            for (int k = 0; k < 3; k++) {
                mma_tf32(C1[k],
                         tf32_raw(v1l[u*3+k] * s2l[0]), tf32_raw(v1h[u*3+k] * s2h[0]),
                         tf32_raw(v1l[u*3+k] * s2l[1]), tf32_raw(v1h[u*3+k] * s2h[1]),
                         wv.x, wv.y);
            }
        }

        // ---- vector stores into own staging rows ----
        // C layout: c0:(g,2t) c1:(g,2t+1) c2:(g+8,2t) c3:(g+8,2t+1)
        *(float2*)(Rlo + 2 * t) = make_float2(C0a[0] + C0b[0], C0a[1] + C0b[1]);
        *(float2*)(Rhi + 2 * t) = make_float2(C0a[2] + C0b[2], C0a[3] + C0b[3]);
        // out1: floats 8+6t .. 8+6t+5 = [C1[0..2][0], C1[0..2][1]]
        *(float2*)(Rlo + 8 + 6 * t)     = make_float2(C1[0][0], C1[1][0]);
        *(float2*)(Rlo + 8 + 6 * t + 2) = make_float2(C1[2][0], C1[0][1]);
        *(float2*)(Rlo + 8 + 6 * t + 4) = make_float2(C1[1][1], C1[2][1]);
        *(float2*)(Rhi + 8 + 6 * t)     = make_float2(C1[0][2], C1[1][2]);
        *(float2*)(Rhi + 8 + 6 * t + 2) = make_float2(C1[2][2], C1[0][3]);
        *(float2*)(Rhi + 8 + 6 * t + 4) = make_float2(C1[1][3], C1[2][3]);
    }

    __syncthreads();

    // ---- coalesced drain (vector LDS.128) ----
    {
        float4* go = (float4*)(out + eBase * 32);
#pragma unroll
        for (int c = 0; c < 8; c++) {
            int lin = tid + c * 128;
            int e = lin >> 3, j = (lin & 7) << 2;
            go[lin] = *(const float4*)(st + e * EPITCH + j);
        }
    }
}

extern "C" void kernel_launch(void* const* d_in, const int* in_sizes, int n_in,
                              void* d_out, int out_size)
{
    const float* x1 = (const float*)d_in[0];
    const float* x2 = (const float*)d_in[1];
    const float* wt = (const float*)d_in[2];
    float* out = (float*)d_out;

    int nelem  = out_size / 32;                            // 2^20
    int blocks = nelem / 128;                              // 128 elements/block
    size_t smem = (2048 + 128 * EPITCH) * sizeof(float);   // 43008 B

    static bool attr_set = false;
    if (!attr_set) {
        cudaFuncSetAttribute(fctp_kernel,
                             cudaFuncAttributeMaxDynamicSharedMemorySize,
                             (int)smem);
        attr_set = true;
    }
    fctp_kernel<<<blocks, 128, smem>>>(x1, x2, wt, out);
}

// round 14
// speedup vs baseline: 1.7198x; 1.1256x over previous
#include <cuda_runtime.h>

// FullyConnectedTensorProduct: B=2^20, MUL=8, DIM=32, 4 paths of 8x8x8.
// R14: R13 + A-forming packed across the lo/hi element axis via f32x2
// (pair halves ARE the MMA a-operands -> forming ops halve), and GEMM1/GEMM2
// interleaved per kk for 5 independent MMA chains (distance >= 4).
// Weights paired (b0,b1) in smem (LDS.64); staging/stores as R13 (EPITCH 68).

typedef unsigned int u32;
typedef unsigned long long u64;

#define ALPHA_F     0.08838834764831845f   /* 1/sqrt(128) */
#define INV_SQRT3_F 0.5773502691896258f
#define EPITCH 68

static __device__ __forceinline__ u32 cvt_tf32(float f) {
    u32 r;
    asm("cvt.rna.tf32.f32 %0, %1;" : "=r"(r) : "f"(f));
    return r;
}
static __device__ __forceinline__ u64 pk2(float lo, float hi) {
    u64 r;
    asm("mov.b64 %0, {%1, %2};"
        : "=l"(r) : "r"(__float_as_uint(lo)), "r"(__float_as_uint(hi)));
    return r;
}
static __device__ __forceinline__ void upk2u(u64 v, u32& lo, u32& hi) {
    asm("mov.b64 {%0, %1}, %2;" : "=r"(lo), "=r"(hi) : "l"(v));
}
static __device__ __forceinline__ u64 fmul2(u64 a, u64 b) {
    u64 d;
    asm("mul.rn.f32x2 %0, %1, %2;" : "=l"(d) : "l"(a), "l"(b));
    return d;
}
static __device__ __forceinline__ u64 ffma2(u64 a, u64 b, u64 c) {
    u64 d;
    asm("fma.rn.f32x2 %0, %1, %2, %3;" : "=l"(d) : "l"(a), "l"(b), "l"(c));
    return d;
}

// MMA with packed A: A01 = (a0,a1), A23 = (a2,a3); raw-bit tf32 A operands.
static __device__ __forceinline__ void mma_p(float c[4], u64 A01, u64 A23,
                                             uint2 wv)
{
    u32 a0, a1, a2, a3;
    upk2u(A01, a0, a1);
    upk2u(A23, a2, a3);
    asm("mma.sync.aligned.m16n8k8.row.col.f32.tf32.tf32.f32 "
        "{%0,%1,%2,%3}, {%4,%5,%6,%7}, {%8,%9}, {%0,%1,%2,%3};"
        : "+f"(c[0]), "+f"(c[1]), "+f"(c[2]), "+f"(c[3])
        : "r"(a0), "r"(a1), "r"(a2), "r"(a3), "r"(wv.x), "r"(wv.y));
}

__global__ __launch_bounds__(128, 4)
void fctp_kernel(const float* __restrict__ x1,
                 const float* __restrict__ x2,
                 const float* __restrict__ wt,
                 float* __restrict__ out)
{
    extern __shared__ __align__(16) float smem[];
    uint2* wsp = (uint2*)smem;        // 1024 pairs (b0,b1) per (kk,t,g)
    float* st  = smem + 2048;         // 128 * EPITCH staging

    const int tid = threadIdx.x;
    const size_t eBase = (size_t)blockIdx.x * 128;

    // ---- stage weights paired: float pos i = kk*64 + (t*8+g)*2 + j,
    //      src col c = kk*8 + t + 4*j, src idx = c*8 + g. INV_SQRT3 on W1.
#pragma unroll
    for (int c = 0; c < 16; c++) {
        int i  = tid + c * 128;
        int kk = i >> 6;
        int p  = (i >> 1) & 31;
        int j  = i & 1;
        int t_ = p >> 3, g_ = p & 7;
        int src = (kk * 8 + t_ + 4 * j) * 8 + g_;
        float s = ((src >> 9) == 1) ? INV_SQRT3_F : 1.0f;
        ((u32*)smem)[i] = cvt_tf32(__ldg(wt + src) * s);
    }

    // ---- stage inputs (STS.128): x1*ALPHA at [0..31], x2 at [32..63] ----
    {
        const float4* g1 = (const float4*)(x1 + eBase * 32);
        const float4* g2 = (const float4*)(x2 + eBase * 32);
#pragma unroll
        for (int c = 0; c < 8; c++) {
            int lin = tid + c * 128;
            int e = lin >> 3, j = (lin & 7) << 2;
            float4 a = g1[lin];
            a.x *= ALPHA_F; a.y *= ALPHA_F; a.z *= ALPHA_F; a.w *= ALPHA_F;
            *(float4*)(st + e * EPITCH + j) = a;
            float4 b = g2[lin];
            *(float4*)(st + e * EPITCH + 32 + j) = b;
        }
    }
    __syncthreads();

    const int lane = tid & 31;
    const int g = lane >> 2;
    const int t = lane & 3;
    const int wBase = (tid >> 5) * 32;
    const int wIdx = t * 8 + g;

#pragma unroll
    for (int rb = 0; rb < 2; rb++) {
        float* Rlo = st + (wBase + rb * 16 + g) * EPITCH;
        float* Rhi = Rlo + 8 * EPITCH;

        // ---- packed input caches (lo,hi) ----
        u64 s1p[8], v1p[8][3], s2p[2], v2p[2][3];
        {
            float4 lq0 = *(const float4*)(Rlo + 0);
            float4 lq1 = *(const float4*)(Rlo + 4);
            float4 hq0 = *(const float4*)(Rhi + 0);
            float4 hq1 = *(const float4*)(Rhi + 4);
            s1p[0] = pk2(lq0.x, hq0.x); s1p[1] = pk2(lq0.y, hq0.y);
            s1p[2] = pk2(lq0.z, hq0.z); s1p[3] = pk2(lq0.w, hq0.w);
            s1p[4] = pk2(lq1.x, hq1.x); s1p[5] = pk2(lq1.y, hq1.y);
            s1p[6] = pk2(lq1.z, hq1.z); s1p[7] = pk2(lq1.w, hq1.w);
        }
#pragma unroll
        for (int q = 0; q < 6; q++) {
            float4 a = *(const float4*)(Rlo + 8 + 4 * q);
            float4 b = *(const float4*)(Rhi + 8 + 4 * q);
            ((u64*)v1p)[4 * q + 0] = pk2(a.x, b.x);
            ((u64*)v1p)[4 * q + 1] = pk2(a.y, b.y);
            ((u64*)v1p)[4 * q + 2] = pk2(a.z, b.z);
            ((u64*)v1p)[4 * q + 3] = pk2(a.w, b.w);
        }
#pragma unroll
        for (int j = 0; j < 2; j++) {
            int v = t + 4 * j;
            s2p[j] = pk2(Rlo[32 + v], Rhi[32 + v]);
#pragma unroll
            for (int k = 0; k < 3; k++)
                v2p[j][k] = pk2(Rlo[40 + v * 3 + k], Rhi[40 + v * 3 + k]);
        }

        float C0a[4] = {0.f, 0.f, 0.f, 0.f};
        float C0b[4] = {0.f, 0.f, 0.f, 0.f};
        float C1[3][4] = {};

        // ---- kk 0..7: s1-based halves of GEMM1 and GEMM2, interleaved ----
#pragma unroll
        for (int kk = 0; kk < 8; kk++) {
            uint2 wv1 = wsp[kk * 32 + wIdx];
            uint2 wv2 = wsp[(16 + kk) * 32 + wIdx];
            mma_p(C0a, fmul2(s1p[kk], s2p[0]), fmul2(s1p[kk], s2p[1]), wv1);
#pragma unroll
            for (int k = 0; k < 3; k++)
                mma_p(C1[k], fmul2(s1p[kk], v2p[0][k]),
                             fmul2(s1p[kk], v2p[1][k]), wv2);
        }

        // ---- kk 8..15: v1-based halves, interleaved ----
#pragma unroll
        for (int kk = 8; kk < 16; kk++) {
            int u = kk - 8;
            uint2 wv1 = wsp[kk * 32 + wIdx];
            uint2 wv2 = wsp[(16 + kk) * 32 + wIdx];
            u64 P0 = fmul2(v1p[u][0], v2p[0][0]);
            P0 = ffma2(v1p[u][1], v2p[0][1], P0);
            P0 = ffma2(v1p[u][2], v2p[0][2], P0);
            u64 P1 = fmul2(v1p[u][0], v2p[1][0]);
            P1 = ffma2(v1p[u][1], v2p[1][1], P1);
            P1 = ffma2(v1p[u][2], v2p[1][2], P1);
            mma_p(C0b, P0, P1, wv1);
#pragma unroll
            for (int k = 0; k < 3; k++)
                mma_p(C1[k], fmul2(v1p[u][k], s2p[0]),
                             fmul2(v1p[u][k], s2p[1]), wv2);
        }

        // ---- vector stores into own staging rows (same mapping as R13) ----
        *(float2*)(Rlo + 2 * t) = make_float2(C0a[0] + C0b[0], C0a[1] + C0b[1]);
        *(float2*)(Rhi + 2 * t) = make_float2(C0a[2] + C0b[2], C0a[3] + C0b[3]);
        *(float2*)(Rlo + 8 + 6 * t)     = make_float2(C1[0][0], C1[1][0]);
        *(float2*)(Rlo + 8 + 6 * t + 2) = make_float2(C1[2][0], C1[0][1]);
        *(float2*)(Rlo + 8 + 6 * t + 4) = make_float2(C1[1][1], C1[2][1]);
        *(float2*)(Rhi + 8 + 6 * t)     = make_float2(C1[0][2], C1[1][2]);
        *(float2*)(Rhi + 8 + 6 * t + 2) = make_float2(C1[2][2], C1[0][3]);
        *(float2*)(Rhi + 8 + 6 * t + 4) = make_float2(C1[1][3], C1[2][3]);
    }

    __syncthreads();

    // ---- coalesced drain (LDS.128 -> STG.128) ----
    {
        float4* go = (float4*)(out + eBase * 32);
#pragma unroll
        for (int c = 0; c < 8; c++) {
            int lin = tid + c * 128;
            int e = lin >> 3, j = (lin & 7) << 2;
            go[lin] = *(const float4*)(st + e * EPITCH + j);
        }
    }
}

extern "C" void kernel_launch(void* const* d_in, const int* in_sizes, int n_in,
                              void* d_out, int out_size)
{
    const float* x1 = (const float*)d_in[0];
    const float* x2 = (const float*)d_in[1];
    const float* wt = (const float*)d_in[2];
    float* out = (float*)d_out;

    int nelem  = out_size / 32;                            // 2^20
    int blocks = nelem / 128;                              // 128 elements/block
    size_t smem = (2048 + 128 * EPITCH) * sizeof(float);   // 43008 B

    static bool attr_set = false;
    if (!attr_set) {
        cudaFuncSetAttribute(fctp_kernel,
                             cudaFuncAttributeMaxDynamicSharedMemorySize,
                             (int)smem);
        attr_set = true;
    }
    fctp_kernel<<<blocks, 128, smem>>>(x1, x2, wt, out);
}